// round 8
// baseline (speedup 1.0000x reference)
#include <cuda_runtime.h>

// KANN_31379031064675 — 2-layer LagrangeKANN.
// Lane owns one sample per 32-group; walks widths (w, w+32) over 32 iters.
// Layer 1: expanded float4 table (64 KB), 2 LDS.128 + 8 FMA/iter (basis per group).
// Layer 2: monomial float4 table (64 KB), 3-FMA Horner.
// Element index via magic-number floor with the clamp in [0,63] (NOT -0.5: the
// fp32 grid has 0.5-spacing below 2^23, so z<0 produced mantissa 0x7FFFFF ->
// e=63 garbage — the rounds-5/6/7 failure). With z in [0,63]:
//   y  = asm_add(clamp(fma(t,64,-0.5), 0, 63), 2^23)   (spacing-1 region, RN = floor)
//   e  = bits(y) & 63                                   (in-bounds by construction)
//   xt = fma(t, 128, fma(y, -2, 2^24-1))                (== 128t - 2e - 1, exact)

__device__ __forceinline__ float magic_add(float z) {
    float y;
    asm("add.f32 %0, %1, %2;" : "=f"(y) : "f"(z), "f"(8388608.0f));
    return y;
}

__global__ void __launch_bounds__(1024, 1) kann_kernel(
    const float* __restrict__ x,
    const float* __restrict__ w_inner,
    const float* __restrict__ w_outer,
    float* __restrict__ out, int n)
{
    extern __shared__ float smem[];
    float* T1f = smem;           // 16384 floats: float4 idx = e*64 + h*32 + w
    float* T2f = smem + 16384;   // 16384 floats: float4 idx = e*64 + k
    float* S   = smem + 16384;   // staging scratch (16384 >= 12352)

    const int tid = threadIdx.x;
    const int nt = blockDim.x;

    // ---------------- build ----------------
    for (int f = tid; f < 12352; f += nt) S[f] = w_inner[f];
    __syncthreads();
    // layer-1 quads: c = {-9/16, 27/16, -27/16, 9/16}
    #pragma unroll
    for (int r = 0; r < 4; ++r) {
        int f = tid + r * nt;
        if (f < 4096) {
            int w = f & 31, h = (f >> 5) & 1, e = f >> 6;
            int j = 3 * e + 2 * h;
            float cA = h ? -1.6875f : -0.5625f;
            float cB = h ?  0.5625f :  1.6875f;
            ((float4*)T1f)[f] = make_float4(
                cA * S[w * 193 + j],        cA * S[(w + 32) * 193 + j],
                cB * S[w * 193 + j + 1],    cB * S[(w + 32) * 193 + j + 1]);
        }
    }
    __syncthreads();
    for (int f = tid; f < 12352; f += nt) S[f] = w_outer[f];
    __syncthreads();
    float a[4][4];
    #pragma unroll
    for (int r = 0; r < 4; ++r) {
        int f = tid + r * nt;
        if (f < 4096) {
            int k = f & 63, e = f >> 6;
            const float* wp = S + k * 193 + 3 * e;
            float u0 = -0.5625f * wp[0], u1 = 1.6875f * wp[1];
            float u2 = -1.6875f * wp[2], u3 = 0.5625f * wp[3];
            a[r][3] = (u0 + u1) + (u2 + u3);
            a[r][2] = (u3 - u0) + (1.0f / 3.0f) * (u2 - u1);
            a[r][1] = -(u1 + u2) - (1.0f / 9.0f) * (u0 + u3);
            a[r][0] = (1.0f / 3.0f) * (u1 - u2) + (1.0f / 9.0f) * (u0 - u3);
        }
    }
    __syncthreads();
    #pragma unroll
    for (int r = 0; r < 4; ++r) {
        int f = tid + r * nt;
        if (f < 4096) {
            int k = f & 63, e = f >> 6;
            ((float4*)T2f)[e * 64 + k] = make_float4(a[r][0], a[r][1], a[r][2], a[r][3]);
        }
    }
    __syncthreads();

    // ---------------- main ----------------
    const float4* __restrict__ T1v = (const float4*)T1f;
    const float4* __restrict__ T2v = (const float4*)T2f;

    const int lane = tid & 31;
    const int wid = tid >> 5;
    const int nwarp = gridDim.x * (nt >> 5);
    const int gwarp = wid * gridDim.x + blockIdx.x;
    const int ngroups = n >> 5;

    for (int g = gwarp; g < ngroups; g += nwarp) {
        const int base = g << 5;
        const float xv = x[base + lane];

        // per-group layer-1 params (z clamped to [0,63]!)
        float z1 = fmaf(xv, 64.0f, -0.5f);
        z1 = fminf(fmaxf(z1, 0.0f), 63.0f);
        const float y1 = magic_add(z1);
        const int b1 = (__float_as_int(y1) & 63) << 6;
        const float xt = fmaf(xv, 128.0f, fmaf(y1, -2.0f, 16777215.0f));

        // Lagrange basis products (constants folded into the table)
        const float p = xt + 1.0f;
        const float q = xt + (1.0f / 3.0f);
        const float r = xt - (1.0f / 3.0f);
        const float s = xt - 1.0f;
        const float rs = r * s, pq = p * q;
        const float ph0 = q * rs;
        const float ph1 = p * rs;
        const float ph2 = pq * s;
        const float ph3 = pq * r;

        float accA = 0.0f, accB = 0.0f;
        #pragma unroll 4
        for (int i = 0; i < 32; ++i) {
            const int w = (lane + i) & 31;

            // layer 1: 2 LDS.128 + 8 FMA for widths (w, w+32)
            const float4 qa = T1v[b1 + w];
            const float4 qb = T1v[b1 + 32 + w];
            const float tA = fmaf(ph3, qb.z, fmaf(ph2, qb.x, fmaf(ph1, qa.z, ph0 * qa.x)));
            const float tB = fmaf(ph3, qb.w, fmaf(ph2, qb.y, fmaf(ph1, qa.w, ph0 * qa.y)));

            // layer 2, width w
            float zA = fmaf(tA, 64.0f, -0.5f);
            zA = fminf(fmaxf(zA, 0.0f), 63.0f);
            const float yA = magic_add(zA);
            const int eA = __float_as_int(yA) & 63;
            const float xtA = fmaf(tA, 128.0f, fmaf(yA, -2.0f, 16777215.0f));
            const float4 dA = T2v[(eA << 6) + w];
            accA += fmaf(fmaf(fmaf(dA.w, xtA, dA.z), xtA, dA.y), xtA, dA.x);

            // layer 2, width w+32
            float zB = fmaf(tB, 64.0f, -0.5f);
            zB = fminf(fmaxf(zB, 0.0f), 63.0f);
            const float yB = magic_add(zB);
            const int eB = __float_as_int(yB) & 63;
            const float xtB = fmaf(tB, 128.0f, fmaf(yB, -2.0f, 16777215.0f));
            const float4 dB = T2v[(eB << 6) + 32 + w];
            accB += fmaf(fmaf(fmaf(dB.w, xtB, dB.z), xtB, dB.y), xtB, dB.x);
        }
        out[base + lane] = accA + accB;
    }
}

extern "C" void kernel_launch(void* const* d_in, const int* in_sizes, int n_in,
                              void* d_out, int out_size) {
    const float* x  = (const float*)d_in[0];
    const float* wi = (const float*)d_in[1];
    const float* wo = (const float*)d_in[2];
    float* out = (float*)d_out;
    const int n = in_sizes[0];

    const int smem_bytes = 2 * 16384 * sizeof(float);  // 128 KB
    cudaFuncSetAttribute(kann_kernel, cudaFuncAttributeMaxDynamicSharedMemorySize,
                         smem_bytes);
    kann_kernel<<<148, 1024, smem_bytes>>>(x, wi, wo, out, n);
}